// round 11
// baseline (speedup 1.0000x reference)
#include <cuda_runtime.h>
#include <cstdint>
#include <cstddef>

#define N_NODES 50000
#define N_EDGES 1600000
#define DIM 64
#define HEADS 8
#define SCAN_BS 512
#define SCAN_NB 98          // ceil(50000/512)

// Scratch (device globals: no allocation allowed)
__device__ float g_Q[N_NODES * DIM];
__device__ float g_K[N_NODES * DIM];
__device__ float g_V[N_NODES * DIM];
__device__ float g_accum[N_NODES * DIM];          // normalized attn_out
__device__ float g_bias[(size_t)N_EDGES * HEADS]; // bias in SORTED edge order
__device__ int   g_hist[N_NODES];
__device__ int   g_rs[SCAN_NB * SCAN_BS];
__device__ int   g_bsum[SCAN_NB];
__device__ int   g_rowstart[N_NODES + 1];
__device__ int   g_cursor[N_NODES];
__device__ int   g_src[N_EDGES];                  // source node per sorted edge
__device__ int   g_pos[N_EDGES];                  // orig edge -> sorted position

typedef unsigned long long u64;

// ---------------------------------------------------------------------------
// f32x2 packed math (sm_103a) + MUFU approx helpers
// ---------------------------------------------------------------------------
__device__ __forceinline__ u64 pk2(float lo, float hi) {
    u64 r; asm("mov.b64 %0,{%1,%2};" : "=l"(r) : "f"(lo), "f"(hi)); return r;
}
__device__ __forceinline__ u64 bc2(float x) { return pk2(x, x); }
__device__ __forceinline__ void upk2(u64 v, float& lo, float& hi) {
    asm("mov.b64 {%0,%1},%2;" : "=f"(lo), "=f"(hi) : "l"(v));
}
__device__ __forceinline__ u64 fma2(u64 a, u64 b, u64 c) {
    u64 d; asm("fma.rn.f32x2 %0,%1,%2,%3;" : "=l"(d) : "l"(a), "l"(b), "l"(c)); return d;
}
__device__ __forceinline__ float ex2f(float x) {
    float r; asm("ex2.approx.f32 %0,%1;" : "=f"(r) : "f"(x)); return r;
}
__device__ __forceinline__ float rcpf(float x) {
    float r; asm("rcp.approx.f32 %0,%1;" : "=f"(r) : "f"(x)); return r;
}
__device__ __forceinline__ float siluf(float x) {
    float e = ex2f(-1.4426950408889634f * x);
    return x * rcpf(1.0f + e);
}

// ---------------------------------------------------------------------------
// Sort machinery: histogram -> exclusive scan -> scatter
// ---------------------------------------------------------------------------
__global__ void zero_hist_kernel() {
    int idx = blockIdx.x * 256 + threadIdx.x;
    if (idx < N_NODES) g_hist[idx] = 0;
}

__global__ void hist_kernel(const int* __restrict__ ei) {
    int e = blockIdx.x * 512 + threadIdx.x;
    int j = ei[N_EDGES + e];
    atomicAdd(&g_hist[j], 1);
}

__global__ void __launch_bounds__(SCAN_BS) scanA_kernel() {
    __shared__ int s[SCAN_BS];
    int t   = threadIdx.x;
    int gid = blockIdx.x * SCAN_BS + t;
    int v   = (gid < N_NODES) ? g_hist[gid] : 0;
    s[t] = v;
    __syncthreads();
#pragma unroll
    for (int off = 1; off < SCAN_BS; off <<= 1) {
        int u = (t >= off) ? s[t - off] : 0;
        __syncthreads();
        s[t] += u;
        __syncthreads();
    }
    if (gid < N_NODES) g_rs[gid] = s[t] - v;       // exclusive within block
    if (t == SCAN_BS - 1) g_bsum[blockIdx.x] = s[t];
}

// scanC: every block redundantly scans the 98 block sums in smem (cheap),
// takes its own exclusive offset, and writes rowstart/cursor.
__global__ void __launch_bounds__(SCAN_BS) scanC_kernel() {
    __shared__ int sb[128];
    __shared__ int boff_s;
    int t = threadIdx.x;
    int orig = 0;
    if (t < 128) {
        int v = (t < SCAN_NB) ? g_bsum[t] : 0;
        sb[t] = v; orig = v;
    }
    __syncthreads();
#pragma unroll
    for (int off = 1; off < 128; off <<= 1) {
        int u = (t >= off && t < 128) ? sb[t - off] : 0;
        __syncthreads();
        if (t < 128) sb[t] += u;
        __syncthreads();
    }
    if (t == (int)blockIdx.x) boff_s = sb[t] - orig;   // exclusive prefix
    __syncthreads();
    int boff = boff_s;
    int gid = blockIdx.x * SCAN_BS + t;
    if (gid < N_NODES) {
        int rs = g_rs[gid] + boff;
        g_rowstart[gid] = rs;
        g_cursor[gid]   = rs;
    }
    if (gid == 0) g_rowstart[N_NODES] = N_EDGES;
}

__global__ void scatter_kernel(const int* __restrict__ ei) {
    int e = blockIdx.x * 512 + threadIdx.x;
    int i = ei[e];
    int j = ei[N_EDGES + e];
    int p = atomicAdd(&g_cursor[j], 1);
    g_src[p] = i;
    g_pos[e] = p;
}

// ---------------------------------------------------------------------------
// QKV projection: x[N,64] @ {WQ,WK,WV}[64,64] + b  (f32x2 column pairs)
// ---------------------------------------------------------------------------
__global__ void __launch_bounds__(192) qkv_kernel(
    const float* __restrict__ x,
    const float* __restrict__ WQ, const float* __restrict__ bQ,
    const float* __restrict__ WK, const float* __restrict__ bK,
    const float* __restrict__ WV, const float* __restrict__ bV) {
    __shared__ float xs[32 * 64];
    int tid = threadIdx.x;
    int rg  = tid / 96;
    int cp  = tid % 96;
    int sel = cp >> 5;
    int cc  = (cp & 31) * 2;
    const float* W  = (sel == 0) ? WQ : ((sel == 1) ? WK : WV);
    const float* bb = (sel == 0) ? bQ : ((sel == 1) ? bK : bV);
    float* outp     = (sel == 0) ? g_Q : ((sel == 1) ? g_K : g_V);

    u64 w[64];
#pragma unroll
    for (int k = 0; k < 64; k++) w[k] = *(const u64*)(W + k * 64 + cc);
    u64 bias2 = pk2(bb[cc], bb[cc + 1]);

    int row0 = blockIdx.x * 32;
    for (int idx = tid; idx < 32 * 16; idx += 192) {
        int r = idx >> 4, q = idx & 15;
        if (row0 + r < N_NODES)
            ((float4*)xs)[idx] = ((const float4*)x)[(size_t)(row0 + r) * 16 + q];
    }
    __syncthreads();

#pragma unroll 4
    for (int r = 0; r < 16; r++) {
        int lr  = rg * 16 + r;
        int row = row0 + lr;
        u64 acc = bias2;
        const float4* xr = (const float4*)&xs[lr * 64];
#pragma unroll
        for (int k4 = 0; k4 < 16; k4++) {
            float4 xv = xr[k4];
            acc = fma2(bc2(xv.x), w[k4 * 4 + 0], acc);
            acc = fma2(bc2(xv.y), w[k4 * 4 + 1], acc);
            acc = fma2(bc2(xv.z), w[k4 * 4 + 2], acc);
            acc = fma2(bc2(xv.w), w[k4 * 4 + 3], acc);
        }
        if (row < N_NODES) *(u64*)(outp + (size_t)row * 64 + cc) = acc;
    }
}

// ---------------------------------------------------------------------------
// Edge bias MLP: 1 edge per thread, 256 threads/block.
// Halved register pressure vs 2-edge version (~120 regs) -> 512 thr/SM
// (4 warps/SMSP) so the per-k LDS weight bursts are latency-hidden.
// Writes bias to SORTED edge position (g_pos).
// ---------------------------------------------------------------------------
__global__ void __launch_bounds__(256) bias_kernel(
    const float* __restrict__ edge_attr,
    const float* __restrict__ We1, const float* __restrict__ be1,
    const float* __restrict__ We2, const float* __restrict__ be2) {
    __shared__ float W1s[32 * 32];
    __shared__ float W2s[32 * 8];
    __shared__ float be1s[32];
    __shared__ float be2s[8];
    int tid = threadIdx.x;
    for (int idx = tid; idx < 1024; idx += 256) W1s[idx] = We1[idx];
    W2s[tid] = We2[tid];                 // exactly 256 elements
    if (tid < 32) be1s[tid] = be1[tid];
    if (tid < 8)  be2s[tid] = be2[tid];
    __syncthreads();

    int e = blockIdx.x * 256 + tid;

    float4 A[8];
#pragma unroll
    for (int q = 0; q < 8; q++)
        A[q] = ((const float4*)edge_attr)[(size_t)e * 8 + q];

    u64 acc[16];
#pragma unroll
    for (int c2 = 0; c2 < 16; c2++)
        acc[c2] = *(const u64*)&be1s[2 * c2];

#pragma unroll
    for (int k = 0; k < 32; k++) {
        u64 w[16];
#pragma unroll
        for (int q = 0; q < 8; q++) {
            ulonglong2 t = *(const ulonglong2*)&W1s[k * 32 + q * 4];
            w[2 * q] = t.x; w[2 * q + 1] = t.y;
        }
        float a = ((k & 3) == 0) ? A[k >> 2].x : ((k & 3) == 1) ? A[k >> 2].y
                : ((k & 3) == 2) ? A[k >> 2].z : A[k >> 2].w;
        u64 ap = bc2(a);
#pragma unroll
        for (int c2 = 0; c2 < 16; c2++)
            acc[c2] = fma2(ap, w[c2], acc[c2]);
    }

    u64 o[4];
#pragma unroll
    for (int p = 0; p < 4; p++)
        o[p] = *(const u64*)&be2s[2 * p];

#pragma unroll
    for (int c2 = 0; c2 < 16; c2++) {
        float s0, s1;
        upk2(acc[c2], s0, s1);
        s0 = siluf(s0); s1 = siluf(s1);
        {   // hidden unit c = 2*c2
            ulonglong2 ta = *(const ulonglong2*)&W2s[(2 * c2) * 8];
            ulonglong2 tb = *(const ulonglong2*)&W2s[(2 * c2) * 8 + 4];
            u64 sp = bc2(s0);
            o[0] = fma2(sp, ta.x, o[0]); o[1] = fma2(sp, ta.y, o[1]);
            o[2] = fma2(sp, tb.x, o[2]); o[3] = fma2(sp, tb.y, o[3]);
        }
        {   // hidden unit c = 2*c2+1
            ulonglong2 ta = *(const ulonglong2*)&W2s[(2 * c2 + 1) * 8];
            ulonglong2 tb = *(const ulonglong2*)&W2s[(2 * c2 + 1) * 8 + 4];
            u64 sp = bc2(s1);
            o[0] = fma2(sp, ta.x, o[0]); o[1] = fma2(sp, ta.y, o[1]);
            o[2] = fma2(sp, tb.x, o[2]); o[3] = fma2(sp, tb.y, o[3]);
        }
    }

    int p = g_pos[e];
    ulonglong2 ra; ra.x = o[0]; ra.y = o[1];
    ulonglong2 rb; rb.x = o[2]; rb.y = o[3];
    *(ulonglong2*)(g_bias + (size_t)p * 8)     = ra;
    *(ulonglong2*)(g_bias + (size_t)p * 8 + 4) = rb;
}

// ---------------------------------------------------------------------------
// Edge aggregation (CSR): one warp per destination node, 2 warps per block.
// 4 subwarps x 8 lanes (lane = head). No atomics; register accumulation;
// cross-subwarp shfl reduce; normalized write. Softmax max-shift skipped
// (scores are O(1), exp-safe in fp32).
// ---------------------------------------------------------------------------
__global__ void __launch_bounds__(64) edge_agg_kernel() {
    int j = blockIdx.x * 2 + (threadIdx.x >> 5);
    if (j >= N_NODES) return;
    int lane = threadIdx.x & 31;
    int sub  = lane >> 3;
    int h    = lane & 7;

    int rs = g_rowstart[j];
    int re = g_rowstart[j + 1];

    const float4* Qp = (const float4*)(g_Q + (size_t)j * 64 + h * 8);
    float4 qa = Qp[0], qb = Qp[1];

    float4 ac0 = make_float4(0.f, 0.f, 0.f, 0.f);
    float4 ac1 = make_float4(0.f, 0.f, 0.f, 0.f);
    float ssum = 0.f;

    int p = rs + sub;
    int i_next = (p < re) ? g_src[p] : 0;
    for (; p < re; p += 4) {
        int i = i_next;
        int pn = p + 4;
        if (pn < re) i_next = g_src[pn];        // prefetch next index

        float bias = g_bias[(size_t)p * 8 + h];
        const float4* Kp = (const float4*)(g_K + (size_t)i * 64 + h * 8);
        const float4* Vp = (const float4*)(g_V + (size_t)i * 64 + h * 8);
        float4 ka = Kp[0], kb = Kp[1];
        float4 va = Vp[0], vb = Vp[1];

        float dot = qa.x * ka.x;
        dot = fmaf(qa.y, ka.y, dot);
        dot = fmaf(qa.z, ka.z, dot);
        dot = fmaf(qa.w, ka.w, dot);
        dot = fmaf(qb.x, kb.x, dot);
        dot = fmaf(qb.y, kb.y, dot);
        dot = fmaf(qb.z, kb.z, dot);
        dot = fmaf(qb.w, kb.w, dot);

        float score = fmaf(dot, 0.35355339059327373f, bias);   // 1/sqrt(8)
        float e = ex2f(score * 1.4426950408889634f);           // exp(score)

        ssum += e;
        ac0.x = fmaf(e, va.x, ac0.x); ac0.y = fmaf(e, va.y, ac0.y);
        ac0.z = fmaf(e, va.z, ac0.z); ac0.w = fmaf(e, va.w, ac0.w);
        ac1.x = fmaf(e, vb.x, ac1.x); ac1.y = fmaf(e, vb.y, ac1.y);
        ac1.z = fmaf(e, vb.z, ac1.z); ac1.w = fmaf(e, vb.w, ac1.w);
    }

#define XRED(v) v += __shfl_xor_sync(0xffffffffu, v, 8); \
                v += __shfl_xor_sync(0xffffffffu, v, 16);
    XRED(ssum);
    XRED(ac0.x); XRED(ac0.y); XRED(ac0.z); XRED(ac0.w);
    XRED(ac1.x); XRED(ac1.y); XRED(ac1.z); XRED(ac1.w);
#undef XRED

    if (sub == 0) {
        float inv = rcpf(ssum + 1e-12f);
        float4 w0 = make_float4(ac0.x * inv, ac0.y * inv, ac0.z * inv, ac0.w * inv);
        float4 w1 = make_float4(ac1.x * inv, ac1.y * inv, ac1.z * inv, ac1.w * inv);
        float4* op = (float4*)(g_accum + (size_t)j * 64 + h * 8);
        op[0] = w0;
        op[1] = w1;
    }
}

// ---------------------------------------------------------------------------
// Output: out = g_accum @ WO + bO   (f32x2 column pairs)
// ---------------------------------------------------------------------------
__global__ void __launch_bounds__(128) out_kernel(
    const float* __restrict__ WO, const float* __restrict__ bO,
    float* __restrict__ out) {
    __shared__ float ws[32 * 64];
    int tid  = threadIdx.x;
    int rg   = tid >> 5;
    int cc   = (tid & 31) * 2;
    int row0 = blockIdx.x * 32;

    u64 w[64];
#pragma unroll
    for (int k = 0; k < 64; k++) w[k] = *(const u64*)(WO + k * 64 + cc);
    u64 bias2 = pk2(bO[cc], bO[cc + 1]);

    for (int idx = tid; idx < 512; idx += 128) {
        int r = idx >> 4, q = idx & 15;
        int row = row0 + r;
        float4 v = make_float4(0.f, 0.f, 0.f, 0.f);
        if (row < N_NODES) v = ((const float4*)g_accum)[(size_t)row * 16 + q];
        ((float4*)ws)[idx] = v;
    }
    __syncthreads();

#pragma unroll
    for (int r = 0; r < 8; r++) {
        int lr  = rg * 8 + r;
        int row = row0 + lr;
        u64 acc = bias2;
        const float4* xr = (const float4*)&ws[lr * 64];
#pragma unroll
        for (int k4 = 0; k4 < 16; k4++) {
            float4 xv = xr[k4];
            acc = fma2(bc2(xv.x), w[k4 * 4 + 0], acc);
            acc = fma2(bc2(xv.y), w[k4 * 4 + 1], acc);
            acc = fma2(bc2(xv.z), w[k4 * 4 + 2], acc);
            acc = fma2(bc2(xv.w), w[k4 * 4 + 3], acc);
        }
        if (row < N_NODES) *(u64*)(out + (size_t)row * 64 + cc) = acc;
    }
}

// ---------------------------------------------------------------------------
extern "C" void kernel_launch(void* const* d_in, const int* in_sizes, int n_in,
                              void* d_out, int out_size) {
    const float* x   = (const float*)d_in[0];
    const int*   ei  = (const int*)d_in[1];
    const float* ea  = (const float*)d_in[2];
    const float* WQ  = (const float*)d_in[3];
    const float* bQ  = (const float*)d_in[4];
    const float* WK  = (const float*)d_in[5];
    const float* bK  = (const float*)d_in[6];
    const float* WV  = (const float*)d_in[7];
    const float* bV  = (const float*)d_in[8];
    const float* WO  = (const float*)d_in[9];
    const float* bO  = (const float*)d_in[10];
    const float* We1 = (const float*)d_in[11];
    const float* be1 = (const float*)d_in[12];
    const float* We2 = (const float*)d_in[13];
    const float* be2 = (const float*)d_in[14];

    // counting sort of edges by destination
    zero_hist_kernel<<<(N_NODES + 255) / 256, 256>>>();
    hist_kernel<<<N_EDGES / 512, 512>>>(ei);
    scanA_kernel<<<SCAN_NB, SCAN_BS>>>();
    scanC_kernel<<<SCAN_NB, SCAN_BS>>>();
    scatter_kernel<<<N_EDGES / 512, 512>>>(ei);
    // projections + edge MLP (bias written in sorted order)
    qkv_kernel<<<(N_NODES + 31) / 32, 192>>>(x, WQ, bQ, WK, bK, WV, bV);
    bias_kernel<<<N_EDGES / 256, 256>>>(ea, We1, be1, We2, be2);
    // CSR aggregation + output projection
    edge_agg_kernel<<<(N_NODES + 1) / 2, 64>>>();
    out_kernel<<<(N_NODES + 31) / 32, 128>>>(WO, bO, (float*)d_out);
}

// round 14
// speedup vs baseline: 1.2580x; 1.2580x over previous
#include <cuda_runtime.h>
#include <cstdint>
#include <cstddef>

#define N_NODES 50000
#define N_EDGES 1600000
#define DIM 64
#define HEADS 8
#define SCAN_BS 512
#define SCAN_NB 98          // ceil(50000/512)

// Scratch (device globals: no allocation allowed)
__device__ float g_Q[N_NODES * DIM];
__device__ float g_K[N_NODES * DIM];
__device__ float g_V[N_NODES * DIM];
__device__ float g_accum[N_NODES * DIM];          // normalized attn_out
__device__ float g_bias[(size_t)N_EDGES * HEADS]; // bias in SORTED edge order
__device__ int   g_hist[N_NODES];
__device__ int   g_rs[SCAN_NB * SCAN_BS];
__device__ int   g_bsum[SCAN_NB];
__device__ int   g_rowstart[N_NODES + 1];
__device__ int   g_cursor[N_NODES];
__device__ int   g_src[N_EDGES];                  // source node per sorted edge
__device__ int   g_pos[N_EDGES];                  // orig edge -> sorted position

// Edge-MLP weights in constant memory (filled by async D2D copies each launch).
// All accesses are warp-uniform with compile-time offsets -> LDC/LDCU on the
// constant port, freeing the LSU/smem crossbar in bias_kernel.
__constant__ float c_We1[32 * 32];
__constant__ float c_be1[32];
__constant__ float c_We2[32 * 8];
__constant__ float c_be2[8];

typedef unsigned long long u64;

// ---------------------------------------------------------------------------
// f32x2 packed math (sm_103a) + MUFU approx helpers
// ---------------------------------------------------------------------------
__device__ __forceinline__ u64 pk2(float lo, float hi) {
    u64 r; asm("mov.b64 %0,{%1,%2};" : "=l"(r) : "f"(lo), "f"(hi)); return r;
}
__device__ __forceinline__ u64 bc2(float x) { return pk2(x, x); }
__device__ __forceinline__ void upk2(u64 v, float& lo, float& hi) {
    asm("mov.b64 {%0,%1},%2;" : "=f"(lo), "=f"(hi) : "l"(v));
}
__device__ __forceinline__ u64 fma2(u64 a, u64 b, u64 c) {
    u64 d; asm("fma.rn.f32x2 %0,%1,%2,%3;" : "=l"(d) : "l"(a), "l"(b), "l"(c)); return d;
}
__device__ __forceinline__ float ex2f(float x) {
    float r; asm("ex2.approx.f32 %0,%1;" : "=f"(r) : "f"(x)); return r;
}
__device__ __forceinline__ float rcpf(float x) {
    float r; asm("rcp.approx.f32 %0,%1;" : "=f"(r) : "f"(x)); return r;
}
__device__ __forceinline__ float siluf(float x) {
    float e = ex2f(-1.4426950408889634f * x);
    return x * rcpf(1.0f + e);
}

// ---------------------------------------------------------------------------
// Sort machinery: histogram -> exclusive scan -> scatter
// ---------------------------------------------------------------------------
__global__ void zero_hist_kernel() {
    int idx = blockIdx.x * 256 + threadIdx.x;
    if (idx < N_NODES) g_hist[idx] = 0;
}

__global__ void hist_kernel(const int* __restrict__ ei) {
    int e = blockIdx.x * 512 + threadIdx.x;
    int j = ei[N_EDGES + e];
    atomicAdd(&g_hist[j], 1);
}

__global__ void __launch_bounds__(SCAN_BS) scanA_kernel() {
    __shared__ int s[SCAN_BS];
    int t   = threadIdx.x;
    int gid = blockIdx.x * SCAN_BS + t;
    int v   = (gid < N_NODES) ? g_hist[gid] : 0;
    s[t] = v;
    __syncthreads();
#pragma unroll
    for (int off = 1; off < SCAN_BS; off <<= 1) {
        int u = (t >= off) ? s[t - off] : 0;
        __syncthreads();
        s[t] += u;
        __syncthreads();
    }
    if (gid < N_NODES) g_rs[gid] = s[t] - v;       // exclusive within block
    if (t == SCAN_BS - 1) g_bsum[blockIdx.x] = s[t];
}

// scanC: every block redundantly scans the 98 block sums in smem (cheap),
// takes its own exclusive offset, and writes rowstart/cursor.
__global__ void __launch_bounds__(SCAN_BS) scanC_kernel() {
    __shared__ int sb[128];
    __shared__ int boff_s;
    int t = threadIdx.x;
    int orig = 0;
    if (t < 128) {
        int v = (t < SCAN_NB) ? g_bsum[t] : 0;
        sb[t] = v; orig = v;
    }
    __syncthreads();
#pragma unroll
    for (int off = 1; off < 128; off <<= 1) {
        int u = (t >= off && t < 128) ? sb[t - off] : 0;
        __syncthreads();
        if (t < 128) sb[t] += u;
        __syncthreads();
    }
    if (t == (int)blockIdx.x) boff_s = sb[t] - orig;   // exclusive prefix
    __syncthreads();
    int boff = boff_s;
    int gid = blockIdx.x * SCAN_BS + t;
    if (gid < N_NODES) {
        int rs = g_rs[gid] + boff;
        g_rowstart[gid] = rs;
        g_cursor[gid]   = rs;
    }
    if (gid == 0) g_rowstart[N_NODES] = N_EDGES;
}

__global__ void scatter_kernel(const int* __restrict__ ei) {
    int e = blockIdx.x * 512 + threadIdx.x;
    int i = ei[e];
    int j = ei[N_EDGES + e];
    int p = atomicAdd(&g_cursor[j], 1);
    g_src[p] = i;
    g_pos[e] = p;
}

// ---------------------------------------------------------------------------
// QKV projection: x[N,64] @ {WQ,WK,WV}[64,64] + b  (f32x2 column pairs)
// ---------------------------------------------------------------------------
__global__ void __launch_bounds__(192) qkv_kernel(
    const float* __restrict__ x,
    const float* __restrict__ WQ, const float* __restrict__ bQ,
    const float* __restrict__ WK, const float* __restrict__ bK,
    const float* __restrict__ WV, const float* __restrict__ bV) {
    __shared__ float xs[32 * 64];
    int tid = threadIdx.x;
    int rg  = tid / 96;
    int cp  = tid % 96;
    int sel = cp >> 5;
    int cc  = (cp & 31) * 2;
    const float* W  = (sel == 0) ? WQ : ((sel == 1) ? WK : WV);
    const float* bb = (sel == 0) ? bQ : ((sel == 1) ? bK : bV);
    float* outp     = (sel == 0) ? g_Q : ((sel == 1) ? g_K : g_V);

    u64 w[64];
#pragma unroll
    for (int k = 0; k < 64; k++) w[k] = *(const u64*)(W + k * 64 + cc);
    u64 bias2 = pk2(bb[cc], bb[cc + 1]);

    int row0 = blockIdx.x * 32;
    for (int idx = tid; idx < 32 * 16; idx += 192) {
        int r = idx >> 4, q = idx & 15;
        if (row0 + r < N_NODES)
            ((float4*)xs)[idx] = ((const float4*)x)[(size_t)(row0 + r) * 16 + q];
    }
    __syncthreads();

#pragma unroll 4
    for (int r = 0; r < 16; r++) {
        int lr  = rg * 16 + r;
        int row = row0 + lr;
        u64 acc = bias2;
        const float4* xr = (const float4*)&xs[lr * 64];
#pragma unroll
        for (int k4 = 0; k4 < 16; k4++) {
            float4 xv = xr[k4];
            acc = fma2(bc2(xv.x), w[k4 * 4 + 0], acc);
            acc = fma2(bc2(xv.y), w[k4 * 4 + 1], acc);
            acc = fma2(bc2(xv.z), w[k4 * 4 + 2], acc);
            acc = fma2(bc2(xv.w), w[k4 * 4 + 3], acc);
        }
        if (row < N_NODES) *(u64*)(outp + (size_t)row * 64 + cc) = acc;
    }
}

// ---------------------------------------------------------------------------
// Edge bias MLP: 2 edges/thread (amortizes weight reads over 2x FMA work),
// weights from __constant__ (LDC/LDCU on the constant port -> LSU stays
// idle; no smem staging, no __syncthreads). Writes bias to SORTED position.
// ---------------------------------------------------------------------------
__global__ void __launch_bounds__(128) bias_kernel(
    const float* __restrict__ edge_attr) {
    int tid = threadIdx.x;
    int e0 = (blockIdx.x * 128 + tid) * 2;

    float4 A0[8], A1[8];
#pragma unroll
    for (int q = 0; q < 8; q++) {
        A0[q] = ((const float4*)edge_attr)[(size_t)e0 * 8 + q];
        A1[q] = ((const float4*)edge_attr)[(size_t)e0 * 8 + 8 + q];
    }

    u64 acc0[16], acc1[16];
#pragma unroll
    for (int c2 = 0; c2 < 16; c2++) {
        u64 b = *(const u64*)&c_be1[2 * c2];
        acc0[c2] = b; acc1[c2] = b;
    }

#pragma unroll
    for (int k = 0; k < 32; k++) {
        float a0 = ((k & 3) == 0) ? A0[k >> 2].x : ((k & 3) == 1) ? A0[k >> 2].y
                 : ((k & 3) == 2) ? A0[k >> 2].z : A0[k >> 2].w;
        float a1 = ((k & 3) == 0) ? A1[k >> 2].x : ((k & 3) == 1) ? A1[k >> 2].y
                 : ((k & 3) == 2) ? A1[k >> 2].z : A1[k >> 2].w;
        u64 a0p = bc2(a0), a1p = bc2(a1);
#pragma unroll
        for (int c2 = 0; c2 < 16; c2++) {
            u64 wv = *(const u64*)&c_We1[k * 32 + 2 * c2];
            acc0[c2] = fma2(a0p, wv, acc0[c2]);
            acc1[c2] = fma2(a1p, wv, acc1[c2]);
        }
    }

    u64 o0[4], o1[4];
#pragma unroll
    for (int p = 0; p < 4; p++) {
        u64 b = *(const u64*)&c_be2[2 * p];
        o0[p] = b; o1[p] = b;
    }

#pragma unroll
    for (int c2 = 0; c2 < 16; c2++) {
        float s00, s01, s10, s11;
        upk2(acc0[c2], s00, s01);
        upk2(acc1[c2], s10, s11);
        s00 = siluf(s00); s01 = siluf(s01);
        s10 = siluf(s10); s11 = siluf(s11);
        {   // hidden unit c = 2*c2
            u64 w0 = *(const u64*)&c_We2[(2 * c2) * 8];
            u64 w1 = *(const u64*)&c_We2[(2 * c2) * 8 + 2];
            u64 w2 = *(const u64*)&c_We2[(2 * c2) * 8 + 4];
            u64 w3 = *(const u64*)&c_We2[(2 * c2) * 8 + 6];
            u64 sp0 = bc2(s00), sp1 = bc2(s10);
            o0[0] = fma2(sp0, w0, o0[0]); o0[1] = fma2(sp0, w1, o0[1]);
            o0[2] = fma2(sp0, w2, o0[2]); o0[3] = fma2(sp0, w3, o0[3]);
            o1[0] = fma2(sp1, w0, o1[0]); o1[1] = fma2(sp1, w1, o1[1]);
            o1[2] = fma2(sp1, w2, o1[2]); o1[3] = fma2(sp1, w3, o1[3]);
        }
        {   // hidden unit c = 2*c2+1
            u64 w0 = *(const u64*)&c_We2[(2 * c2 + 1) * 8];
            u64 w1 = *(const u64*)&c_We2[(2 * c2 + 1) * 8 + 2];
            u64 w2 = *(const u64*)&c_We2[(2 * c2 + 1) * 8 + 4];
            u64 w3 = *(const u64*)&c_We2[(2 * c2 + 1) * 8 + 6];
            u64 sp0 = bc2(s01), sp1 = bc2(s11);
            o0[0] = fma2(sp0, w0, o0[0]); o0[1] = fma2(sp0, w1, o0[1]);
            o0[2] = fma2(sp0, w2, o0[2]); o0[3] = fma2(sp0, w3, o0[3]);
            o1[0] = fma2(sp1, w0, o1[0]); o1[1] = fma2(sp1, w1, o1[1]);
            o1[2] = fma2(sp1, w2, o1[2]); o1[3] = fma2(sp1, w3, o1[3]);
        }
    }

    int p0 = g_pos[e0];
    int p1 = g_pos[e0 + 1];
    ulonglong2 r0a; r0a.x = o0[0]; r0a.y = o0[1];
    ulonglong2 r0b; r0b.x = o0[2]; r0b.y = o0[3];
    ulonglong2 r1a; r1a.x = o1[0]; r1a.y = o1[1];
    ulonglong2 r1b; r1b.x = o1[2]; r1b.y = o1[3];
    *(ulonglong2*)(g_bias + (size_t)p0 * 8)     = r0a;
    *(ulonglong2*)(g_bias + (size_t)p0 * 8 + 4) = r0b;
    *(ulonglong2*)(g_bias + (size_t)p1 * 8)     = r1a;
    *(ulonglong2*)(g_bias + (size_t)p1 * 8 + 4) = r1b;
}

// ---------------------------------------------------------------------------
// Edge aggregation (CSR): one warp per destination node, 2 warps per block.
// 4 subwarps x 8 lanes (lane = head). No atomics; register accumulation;
// cross-subwarp shfl reduce; normalized write. Softmax max-shift skipped
// (scores are O(1), exp-safe in fp32).
// ---------------------------------------------------------------------------
__global__ void __launch_bounds__(64) edge_agg_kernel() {
    int j = blockIdx.x * 2 + (threadIdx.x >> 5);
    if (j >= N_NODES) return;
    int lane = threadIdx.x & 31;
    int sub  = lane >> 3;
    int h    = lane & 7;

    int rs = g_rowstart[j];
    int re = g_rowstart[j + 1];

    const float4* Qp = (const float4*)(g_Q + (size_t)j * 64 + h * 8);
    float4 qa = Qp[0], qb = Qp[1];

    float4 ac0 = make_float4(0.f, 0.f, 0.f, 0.f);
    float4 ac1 = make_float4(0.f, 0.f, 0.f, 0.f);
    float ssum = 0.f;

    int p = rs + sub;
    int i_next = (p < re) ? g_src[p] : 0;
    for (; p < re; p += 4) {
        int i = i_next;
        int pn = p + 4;
        if (pn < re) i_next = g_src[pn];        // prefetch next index

        float bias = g_bias[(size_t)p * 8 + h];
        const float4* Kp = (const float4*)(g_K + (size_t)i * 64 + h * 8);
        const float4* Vp = (const float4*)(g_V + (size_t)i * 64 + h * 8);
        float4 ka = Kp[0], kb = Kp[1];
        float4 va = Vp[0], vb = Vp[1];

        float dot = qa.x * ka.x;
        dot = fmaf(qa.y, ka.y, dot);
        dot = fmaf(qa.z, ka.z, dot);
        dot = fmaf(qa.w, ka.w, dot);
        dot = fmaf(qb.x, kb.x, dot);
        dot = fmaf(qb.y, kb.y, dot);
        dot = fmaf(qb.z, kb.z, dot);
        dot = fmaf(qb.w, kb.w, dot);

        float score = fmaf(dot, 0.35355339059327373f, bias);   // 1/sqrt(8)
        float e = ex2f(score * 1.4426950408889634f);           // exp(score)

        ssum += e;
        ac0.x = fmaf(e, va.x, ac0.x); ac0.y = fmaf(e, va.y, ac0.y);
        ac0.z = fmaf(e, va.z, ac0.z); ac0.w = fmaf(e, va.w, ac0.w);
        ac1.x = fmaf(e, vb.x, ac1.x); ac1.y = fmaf(e, vb.y, ac1.y);
        ac1.z = fmaf(e, vb.z, ac1.z); ac1.w = fmaf(e, vb.w, ac1.w);
    }

#define XRED(v) v += __shfl_xor_sync(0xffffffffu, v, 8); \
                v += __shfl_xor_sync(0xffffffffu, v, 16);
    XRED(ssum);
    XRED(ac0.x); XRED(ac0.y); XRED(ac0.z); XRED(ac0.w);
    XRED(ac1.x); XRED(ac1.y); XRED(ac1.z); XRED(ac1.w);
#undef XRED

    if (sub == 0) {
        float inv = rcpf(ssum + 1e-12f);
        float4 w0 = make_float4(ac0.x * inv, ac0.y * inv, ac0.z * inv, ac0.w * inv);
        float4 w1 = make_float4(ac1.x * inv, ac1.y * inv, ac1.z * inv, ac1.w * inv);
        float4* op = (float4*)(g_accum + (size_t)j * 64 + h * 8);
        op[0] = w0;
        op[1] = w1;
    }
}

// ---------------------------------------------------------------------------
// Output: out = g_accum @ WO + bO   (f32x2 column pairs)
// ---------------------------------------------------------------------------
__global__ void __launch_bounds__(128) out_kernel(
    const float* __restrict__ WO, const float* __restrict__ bO,
    float* __restrict__ out) {
    __shared__ float ws[32 * 64];
    int tid  = threadIdx.x;
    int rg   = tid >> 5;
    int cc   = (tid & 31) * 2;
    int row0 = blockIdx.x * 32;

    u64 w[64];
#pragma unroll
    for (int k = 0; k < 64; k++) w[k] = *(const u64*)(WO + k * 64 + cc);
    u64 bias2 = pk2(bO[cc], bO[cc + 1]);

    for (int idx = tid; idx < 512; idx += 128) {
        int r = idx >> 4, q = idx & 15;
        int row = row0 + r;
        float4 v = make_float4(0.f, 0.f, 0.f, 0.f);
        if (row < N_NODES) v = ((const float4*)g_accum)[(size_t)row * 16 + q];
        ((float4*)ws)[idx] = v;
    }
    __syncthreads();

#pragma unroll
    for (int r = 0; r < 8; r++) {
        int lr  = rg * 8 + r;
        int row = row0 + lr;
        u64 acc = bias2;
        const float4* xr = (const float4*)&ws[lr * 64];
#pragma unroll
        for (int k4 = 0; k4 < 16; k4++) {
            float4 xv = xr[k4];
            acc = fma2(bc2(xv.x), w[k4 * 4 + 0], acc);
            acc = fma2(bc2(xv.y), w[k4 * 4 + 1], acc);
            acc = fma2(bc2(xv.z), w[k4 * 4 + 2], acc);
            acc = fma2(bc2(xv.w), w[k4 * 4 + 3], acc);
        }
        if (row < N_NODES) *(u64*)(out + (size_t)row * 64 + cc) = acc;
    }
}

// ---------------------------------------------------------------------------
extern "C" void kernel_launch(void* const* d_in, const int* in_sizes, int n_in,
                              void* d_out, int out_size) {
    const float* x   = (const float*)d_in[0];
    const int*   ei  = (const int*)d_in[1];
    const float* ea  = (const float*)d_in[2];
    const float* WQ  = (const float*)d_in[3];
    const float* bQ  = (const float*)d_in[4];
    const float* WK  = (const float*)d_in[5];
    const float* bK  = (const float*)d_in[6];
    const float* WV  = (const float*)d_in[7];
    const float* bV  = (const float*)d_in[8];
    const float* WO  = (const float*)d_in[9];
    const float* bO  = (const float*)d_in[10];
    const float* We1 = (const float*)d_in[11];
    const float* be1 = (const float*)d_in[12];
    const float* We2 = (const float*)d_in[13];
    const float* be2 = (const float*)d_in[14];

    // edge-MLP weights -> constant memory (async D2D, graph-capturable)
    cudaMemcpyToSymbolAsync(c_We1, We1, 32 * 32 * sizeof(float), 0,
                            cudaMemcpyDeviceToDevice);
    cudaMemcpyToSymbolAsync(c_be1, be1, 32 * sizeof(float), 0,
                            cudaMemcpyDeviceToDevice);
    cudaMemcpyToSymbolAsync(c_We2, We2, 32 * 8 * sizeof(float), 0,
                            cudaMemcpyDeviceToDevice);
    cudaMemcpyToSymbolAsync(c_be2, be2, 8 * sizeof(float), 0,
                            cudaMemcpyDeviceToDevice);

    // counting sort of edges by destination
    zero_hist_kernel<<<(N_NODES + 255) / 256, 256>>>();
    hist_kernel<<<N_EDGES / 512, 512>>>(ei);
    scanA_kernel<<<SCAN_NB, SCAN_BS>>>();
    scanC_kernel<<<SCAN_NB, SCAN_BS>>>();
    scatter_kernel<<<N_EDGES / 512, 512>>>(ei);
    // projections + edge MLP (bias written in sorted order)
    qkv_kernel<<<(N_NODES + 31) / 32, 192>>>(x, WQ, bQ, WK, bK, WV, bV);
    bias_kernel<<<N_EDGES / 256, 128>>>(ea);
    // CSR aggregation + output projection
    edge_agg_kernel<<<(N_NODES + 1) / 2, 64>>>();
    out_kernel<<<(N_NODES + 31) / 32, 128>>>(WO, bO, (float*)d_out);
}